// round 14
// baseline (speedup 1.0000x reference)
#include <cuda_runtime.h>
#include <math.h>

#define BB 2
#define TT 2048
#define HH 12
#define DD 64
#define CC 768
#define NQKV 2304
#define NEG (-1e30f)

// ---------------- scratch (device globals; no allocations allowed) ----------
// W layouts: [kchunk][nblk][16 pair-rows][128 words]
// K layout: natural rows, d-permuted within row (pairs (d, d+4) adjacent)
// V layout: per 64-key tile: [32 pairrows][128 words], word = 2d + lohi
__device__ __align__(16) unsigned g_Wqkv[CC * NQKV];
__device__ __align__(16) unsigned g_Wo[CC * CC];
__device__ __align__(16) unsigned g_Xtf[BB * TT * CC];            // tf32 x
__device__ __align__(16) unsigned g_QKVt[3 * BB * HH * TT * DD];  // tf32
__device__ __align__(16) unsigned g_Otf[BB * TT * CC];            // tf32 O
__device__ __align__(16) float    g_cos[TT * 32];
__device__ __align__(16) float    g_sin[TT * 32];
// split-attention partials (rows t>=1024 only are used)
__device__ __align__(16) float    g_Op[2][BB * TT * CC];
__device__ __align__(16) float    g_m[2][BB * HH * TT];
__device__ __align__(16) float    g_l[2][BB * HH * TT];

// ---------------- helpers ----------------------------------------------------
__device__ __forceinline__ unsigned f2tf(float f) {
    unsigned u;
    asm("cvt.rna.tf32.f32 %0, %1;" : "=r"(u) : "f"(f));
    return u;
}

__device__ __forceinline__ void mma_tf32(
        float& c0, float& c1, float& c2, float& c3,
        unsigned a0, unsigned a1, unsigned a2, unsigned a3,
        unsigned b0, unsigned b1) {
    asm("mma.sync.aligned.m16n8k8.row.col.f32.tf32.tf32.f32 "
        "{%0,%1,%2,%3}, {%4,%5,%6,%7}, {%8,%9}, {%0,%1,%2,%3};"
        : "+f"(c0), "+f"(c1), "+f"(c2), "+f"(c3)
        : "r"(a0), "r"(a1), "r"(a2), "r"(a3), "r"(b0), "r"(b1));
}

__device__ __forceinline__ void cp16(void* sdst, const void* gsrc) {
    unsigned s = (unsigned)__cvta_generic_to_shared(sdst);
    asm volatile("cp.async.cg.shared.global [%0], [%1], 16;" :: "r"(s), "l"(gsrc));
}
#define CP_COMMIT() asm volatile("cp.async.commit_group;")
#define CP_WAIT0()  asm volatile("cp.async.wait_group 0;")

// in-row K permutation: pairs (d, d+4) adjacent within each 8-block
__device__ __forceinline__ int kperm(int d) {
    return (d & ~7) + ((d & 3) << 1) + ((d >> 2) & 1);
}

// ---------------- kernel 0a: pack QKV weights (tf32, pair-interleaved) ------
__global__ void pack_w_k(const float* __restrict__ wq,
                         const float* __restrict__ wk,
                         const float* __restrict__ wv) {
    int idx = blockIdx.x * 256 + threadIdx.x;
    if (idx >= CC * NQKV) return;
    int k = idx / NQKV, n = idx - k * NQKV;
    int which = n / 768, hd = n - which * 768;
    int h = hd >> 6, d = hd & 63;
    const float* w = (which == 0) ? wq : (which == 1) ? wk : wv;
    int kc = k >> 5, kin = k & 31, kt = kin >> 3, kq = kin & 7;
    int qcK = kq & 3, lohi = kq >> 2;
    int nblk = n >> 6, nl = n & 63;
    int gidx = ((kc * 36 + nblk) * 16 + kt * 4 + qcK) * 128 + nl * 2 + lohi;
    g_Wqkv[gidx] = f2tf(w[(h * CC + k) * DD + d]);
}

// ---------------- kernel 0b: W_O pack (pair-interleaved) ---------------------
__global__ void pack_wo_k(const float* __restrict__ wo) {
    int idx = blockIdx.x * 256 + threadIdx.x;
    if (idx >= CC * CC) return;
    int k = idx / CC, n = idx - k * CC;
    int kc = k >> 5, kin = k & 31, kt = kin >> 3, kq = kin & 7;
    int qcK = kq & 3, lohi = kq >> 2;
    int nblk = n >> 6, nl = n & 63;
    int gidx = ((kc * 12 + nblk) * 16 + kt * 4 + qcK) * 128 + nl * 2 + lohi;
    g_Wo[gidx] = f2tf(wo[idx]);
}

// ---------------- kernel 0c: x -> tf32 ---------------------------------------
__global__ void xconv_k(const float* __restrict__ x) {
    int idx = blockIdx.x * 256 + threadIdx.x;
    if (idx >= BB * TT * CC) return;
    g_Xtf[idx] = f2tf(x[idx]);
}

// ---------------- kernel 0d: rope cos/sin table -----------------------------
__global__ void rope_table_k() {
    int idx = blockIdx.x * 256 + threadIdx.x;
    if (idx >= TT * 32) return;
    int t = idx >> 5, i = idx & 31;
    double e = (double)i * 0.41524101186092028;   // log2(10000)/32
    float inv = exp2f((float)(-e));
    float ang = (float)t * inv;
    float s, c;
    sincosf(ang, &s, &c);
    g_cos[idx] = c;
    g_sin[idx] = s;
}

// ---------------- tf32 GEMM: 128x64 tile, chunk 32, cp.async pipelined ------
#define XSTR 36
#define PRSTR 136
#define GEMM_SMEM_UINTS (2 * 128 * XSTR + 2 * 16 * PRSTR)
#define GEMM_SMEM_BYTES (GEMM_SMEM_UINTS * 4)

#define GEMM_CHUNK_MMAS(Xb, Wb)                                              \
    _Pragma("unroll")                                                        \
    for (int kt = 0; kt < 4; kt++) {                                         \
        int abase = (w * 16 + qr) * XSTR + kt * 8 + qc;                      \
        unsigned fa0 = (Xb)[abase];                                          \
        unsigned fa1 = (Xb)[abase + 8 * XSTR];                               \
        unsigned fa2 = (Xb)[abase + 4];                                      \
        unsigned fa3 = (Xb)[abase + 8 * XSTR + 4];                           \
        const unsigned* wrow = &(Wb)[(kt * 4 + qc) * PRSTR + qr * 2];        \
        _Pragma("unroll")                                                    \
        for (int nt = 0; nt < 8; nt++) {                                     \
            uint2 bp = *(const uint2*)&wrow[nt * 16];                        \
            mma_tf32(Cf[nt][0], Cf[nt][1], Cf[nt][2], Cf[nt][3],             \
                     fa0, fa1, fa2, fa3, bp.x, bp.y);                        \
        }                                                                    \
    }

// ---------------- kernel 1: QKV GEMM + bias + RoPE (tf32 mma) ---------------
__global__ __launch_bounds__(256, 3) void qkv_tc_k(
        const float* __restrict__ bq,
        const float* __restrict__ bk,
        const float* __restrict__ bv) {
    extern __shared__ unsigned smg[];
    unsigned* Xs = smg;                        // 2 * 128*36
    unsigned* Ws = smg + 2 * 128 * XSTR;       // 2 * 16*136
    const int tid = threadIdx.x;
    const int w = tid >> 5, lane = tid & 31;
    const int qr = lane >> 2, qc = lane & 3;
    const int m0 = blockIdx.y * 128;
    const int nblk = blockIdx.x;
    const int n0 = nblk * 64;
    const int lrow = tid >> 1, lkb = (tid & 1) << 4;
    const int lkr = tid >> 4, lnb = (tid & 15) << 3;

    {
        unsigned* xd = &Xs[lrow * XSTR + lkb];
        const unsigned* xs = &g_Xtf[(m0 + lrow) * CC + lkb];
#pragma unroll
        for (int q = 0; q < 4; q++) cp16(xd + q * 4, xs + q * 4);
        unsigned* wd = &Ws[lkr * PRSTR + lnb];
        const unsigned* ws = &g_Wqkv[(0 * 36 + nblk) * 16 * 128 + lkr * 128 + lnb];
#pragma unroll
        for (int q = 0; q < 2; q++) cp16(wd + q * 4, ws + q * 4);
        CP_COMMIT();
    }
    CP_WAIT0();
    __syncthreads();

    float Cf[8][4] = {};
    const int NCH = CC / 32;
    for (int c = 0; c < NCH; c++) {
        if (c + 1 < NCH) {
            int k0 = (c + 1) * 32;
            unsigned* Xn = Xs + ((c + 1) & 1) * 128 * XSTR;
            unsigned* Wn = Ws + ((c + 1) & 1) * 16 * PRSTR;
            unsigned* xd = &Xn[lrow * XSTR + lkb];
            const unsigned* xs = &g_Xtf[(m0 + lrow) * CC + k0 + lkb];
#pragma unroll
            for (int q = 0; q < 4; q++) cp16(xd + q * 4, xs + q * 4);
            unsigned* wd = &Wn[lkr * PRSTR + lnb];
            const unsigned* ws =
                &g_Wqkv[((c + 1) * 36 + nblk) * 16 * 128 + lkr * 128 + lnb];
#pragma unroll
            for (int q = 0; q < 2; q++) cp16(wd + q * 4, ws + q * 4);
            CP_COMMIT();
        }
        const unsigned* Xb = Xs + (c & 1) * 128 * XSTR;
        const unsigned* Wb = Ws + (c & 1) * 16 * PRSTR;
        GEMM_CHUNK_MMAS(Xb, Wb)
        CP_WAIT0();
        __syncthreads();
    }

    // epilogue: bias + rope (+0.125 for Q); Q natural, K d-permuted, V paired
    const int which = n0 / 768;
    const int h = (n0 % 768) >> 6;
    const float* bias = (which == 0) ? bq : (which == 1) ? bk : bv;
    const float qscale = (which == 0) ? 0.125f : 1.0f;
    const int r0 = m0 + w * 16 + qr;
#pragma unroll
    for (int nt = 0; nt < 8; nt++) {
        int d = nt * 8 + 2 * qc;
        float bv0 = bias[h * 64 + d], bv1 = bias[h * 64 + d + 1];
        int ii = nt * 4 + qc;
#pragma unroll
        for (int half = 0; half < 2; half++) {
            int r = r0 + half * 8;
            int bb = r >> 11, t = r & 2047;
            float v0 = Cf[nt][2 * half + 0] + bv0;
            float v1 = Cf[nt][2 * half + 1] + bv1;
            if (which < 2) {
                float cth = g_cos[t * 32 + ii];
                float sth = g_sin[t * 32 + ii];
                float nv0 = v0 * cth - v1 * sth;
                float nv1 = v0 * sth + v1 * cth;
                v0 = nv0 * qscale; v1 = nv1 * qscale;
            }
            unsigned* dst = &g_QKVt[((which * BB + bb) * HH + h) * TT * DD];
            if (which == 0) {
                *(uint2*)&dst[t * DD + d] = make_uint2(f2tf(v0), f2tf(v1));
            } else if (which == 1) {
                dst[t * DD + kperm(d)]     = f2tf(v0);
                dst[t * DD + kperm(d + 1)] = f2tf(v1);
            } else {
                int krow = t & 63;
                int base = (t >> 6) * 4096 +
                           ((((krow >> 3) << 2) + (krow & 3)) << 7) +
                           ((krow >> 2) & 1);
                dst[base + 2 * d]       = f2tf(v0);
                dst[base + 2 * (d + 1)] = f2tf(v1);
            }
        }
    }
}

// ---------------- kernel 2: causal flash attention (tf32, split-K balanced) -
#define KSTR 72
#define VPSTR 136
#define PSTR 68
#define ATTN_SMEM_UINTS (2 * 64 * KSTR + 2 * 32 * VPSTR + 8 * 16 * PSTR)
#define ATTN_SMEM_BYTES (ATTN_SMEM_UINTS * 4)

__global__ __launch_bounds__(256) void attn_k() {
    extern __shared__ unsigned smu[];
    unsigned* Ks = smu;                          // 2 * 64*72 (d-paired rows)
    unsigned* Vs = smu + 2 * 64 * KSTR;          // 2 * 32*136 (key-paired rows)
    unsigned* Ps = Vs + 2 * 32 * VPSTR;          // 8 * 16*68

    const int tid = threadIdx.x;
    const int w = tid >> 5, lane = tid & 31;
    const int qr = lane >> 2, qc = lane & 3;

    const int by = blockIdx.y;
    int qi, part, nparts;
    if (by < 16) { qi = 15 - (by >> 1); part = by & 1; nparts = 2; }
    else         { qi = 23 - by;        part = 0;      nparts = 1; }
    const int bh = blockIdx.x;
    const int b = bh / HH, h = bh % HH;
    const int q0 = qi * 128;
    const int njt = 2 * qi + 2;
    const int jn = (nparts == 2) ? (qi + 1) : njt;
    const int j0 = part * jn;

    const unsigned* Qg = g_QKVt + ((0 * BB + b) * HH + h) * TT * DD;
    const unsigned* Kg = g_QKVt + ((1 * BB + b) * HH + h) * TT * DD;
    const unsigned* Vg = g_QKVt + ((2 * BB + b) * HH + h) * TT * DD;

    // prologue: async-fill tile j0
    {
        unsigned* K0 = Ks + (j0 & 1) * 64 * KSTR;
        unsigned* V0 = Vs + (j0 & 1) * 32 * VPSTR;
        const unsigned* ksrc = &Kg[j0 * 4096];
        const unsigned* vsrc = &Vg[j0 * 4096];
#pragma unroll
        for (int i = 0; i < 4; i++) {
            int id = tid + 256 * i;
            int kr = id >> 4, kc16 = (id & 15) << 2;
            cp16(&K0[kr * KSTR + kc16], &ksrc[kr * DD + kc16]);
            int vr = id >> 5, vc16 = (id & 31) << 2;
            cp16(&V0[vr * VPSTR + vc16], &vsrc[vr * 128 + vc16]);
        }
        CP_COMMIT();
    }

    // Q fragments (natural layout, pre-scaled tf32)
    unsigned Qf[8][4];
    {
        const unsigned* qb = &Qg[(q0 + w * 16 + qr) * DD];
#pragma unroll
        for (int kt = 0; kt < 8; kt++) {
            Qf[kt][0] = qb[kt * 8 + qc];
            Qf[kt][1] = qb[8 * DD + kt * 8 + qc];
            Qf[kt][2] = qb[kt * 8 + qc + 4];
            Qf[kt][3] = qb[8 * DD + kt * 8 + qc + 4];
        }
    }

    float Of[8][4] = {};
    float m0 = NEG, m1 = NEG, l0 = 0.0f, l1 = 0.0f;
    unsigned* Pw = Ps + w * 16 * PSTR;

    CP_WAIT0();
    __syncthreads();

    const int jend = j0 + jn;
    for (int j = j0; j < jend; j++) {
        if (j + 1 < jend) {
            unsigned* Kn = Ks + ((j + 1) & 1) * 64 * KSTR;
            unsigned* Vn = Vs + ((j + 1) & 1) * 32 * VPSTR;
            const unsigned* ksrc = &Kg[(j + 1) * 4096];
            const unsigned* vsrc = &Vg[(j + 1) * 4096];
#pragma unroll
            for (int i = 0; i < 4; i++) {
                int id = tid + 256 * i;
                int kr = id >> 4, kc16 = (id & 15) << 2;
                cp16(&Kn[kr * KSTR + kc16], &ksrc[kr * DD + kc16]);
                int vr = id >> 5, vc16 = (id & 31) << 2;
                cp16(&Vn[vr * VPSTR + vc16], &vsrc[vr * 128 + vc16]);
            }
            CP_COMMIT();
        }
        const unsigned* Kb = Ks + (j & 1) * 64 * KSTR;
        const unsigned* Vb = Vs + (j & 1) * 32 * VPSTR;

        // S = Q K^T : uint2 B pairs (d-paired K rows)
        float Sf[8][4] = {};
#pragma unroll
        for (int nt = 0; nt < 8; nt++) {
            const unsigned* krow = &Kb[(nt * 8 + qr) * KSTR + 2 * qc];
#pragma unroll
            for (int kt = 0; kt < 8; kt++) {
                uint2 bp = *(const uint2*)&krow[kt * 8];
                mma_tf32(Sf[nt][0], Sf[nt][1], Sf[nt][2], Sf[nt][3],
                         Qf[kt][0], Qf[kt][1], Qf[kt][2], Qf[kt][3],
                         bp.x, bp.y);
            }
        }

        if (j >= njt - 2) {   // global diagonal tiles
            int r0g = q0 + w * 16 + qr, r1g = r0g + 8;
#pragma unroll
            for (int nt = 0; nt < 8; nt++) {
                int c0g = j * 64 + nt * 8 + 2 * qc;
                if (c0g > r0g)     Sf[nt][0] = NEG;
                if (c0g + 1 > r0g) Sf[nt][1] = NEG;
                if (c0g > r1g)     Sf[nt][2] = NEG;
                if (c0g + 1 > r1g) Sf[nt][3] = NEG;
            }
        }

        // online softmax
        float mx0 = NEG, mx1 = NEG;
#pragma unroll
        for (int nt = 0; nt < 8; nt++) {
            mx0 = fmaxf(mx0, fmaxf(Sf[nt][0], Sf[nt][1]));
            mx1 = fmaxf(mx1, fmaxf(Sf[nt][2], Sf[nt][3]));
        }
        mx0 = fmaxf(mx0, __shfl_xor_sync(0xffffffffu, mx0, 1));
        mx0 = fmaxf(mx0, __shfl_xor_sync(0xffffffffu, mx0, 2));
        mx1 = fmaxf(mx1, __shfl_xor_sync(0xffffffffu, mx1, 1));
        mx1 = fmaxf(mx1, __shfl_xor_sync(0xffffffffu, mx1, 2));
        float mn0 = fmaxf(m0, mx0), mn1 = fmaxf(m1, mx1);
        float al0 = __expf(m0 - mn0), al1 = __expf(m1 - mn1);
        m0 = mn0; m1 = mn1;
        float s0 = 0.0f, s1 = 0.0f;
#pragma unroll
        for (int nt = 0; nt < 8; nt++) {
            Sf[nt][0] = __expf(Sf[nt][0] - mn0); s0 += Sf[nt][0];
            Sf[nt][1] = __expf(Sf[nt][1] - mn0); s0 += Sf[nt][1];
            Sf[nt][2] = __expf(Sf[nt][2] - mn1); s1 += Sf[nt][2];
            Sf[nt][3] = __expf(Sf[nt][3] - mn1); s1 += Sf[nt][3];
        }
        s0 += __shfl_xor_sync(0xffffffffu, s0, 1);
        s0 += __shfl_xor_sync(0xffffffffu, s0, 2);
        s1 += __shfl_xor_sync(0xffffffffu, s1, 1);
        s1 += __shfl_xor_sync(0xffffffffu, s1, 2);
        l0 = l0 * al0 + s0;
        l1 = l1 * al1 + s1;
#pragma unroll
        for (int nt = 0; nt < 8; nt++) {
            Of[nt][0] *= al0; Of[nt][1] *= al0;
            Of[nt][2] *= al1; Of[nt][3] *= al1;
        }

        // P (tf32) to per-warp smem
#pragma unroll
        for (int nt = 0; nt < 8; nt++) {
            unsigned* p0 = &Pw[qr * PSTR + nt * 8 + 2 * qc];
            p0[0] = f2tf(Sf[nt][0]); p0[1] = f2tf(Sf[nt][1]);
            unsigned* p1 = &Pw[(qr + 8) * PSTR + nt * 8 + 2 * qc];
            p1[0] = f2tf(Sf[nt][2]); p1[1] = f2tf(Sf[nt][3]);
        }
        __syncwarp();

        // O += P V : uint2 B pairs (key-paired V rows)
#pragma unroll
        for (int kt = 0; kt < 8; kt++) {
            unsigned a0 = Pw[qr * PSTR + kt * 8 + qc];
            unsigned a1 = Pw[(qr + 8) * PSTR + kt * 8 + qc];
            unsigned a2 = Pw[qr * PSTR + kt * 8 + qc + 4];
            unsigned a3 = Pw[(qr + 8) * PSTR + kt * 8 + qc + 4];
            const unsigned* vrow = &Vb[(kt * 4 + qc) * VPSTR + 2 * qr];
#pragma unroll
            for (int nt = 0; nt < 8; nt++) {
                uint2 bp = *(const uint2*)&vrow[nt * 16];
                mma_tf32(Of[nt][0], Of[nt][1], Of[nt][2], Of[nt][3],
                         a0, a1, a2, a3, bp.x, bp.y);
            }
        }

        CP_WAIT0();
        __syncthreads();
    }

    int r0g = q0 + w * 16 + qr;
    if (nparts == 1) {
        float il0 = 1.0f / l0, il1 = 1.0f / l1;
#pragma unroll
        for (int nt = 0; nt < 8; nt++) {
            int col = h * 64 + nt * 8 + 2 * qc;
            *(uint2*)&g_Otf[(b * TT + r0g) * CC + col] =
                make_uint2(f2tf(Of[nt][0] * il0), f2tf(Of[nt][1] * il0));
            *(uint2*)&g_Otf[(b * TT + r0g + 8) * CC + col] =
                make_uint2(f2tf(Of[nt][2] * il1), f2tf(Of[nt][3] * il1));
        }
    } else {
        float* Op = g_Op[part];
#pragma unroll
        for (int nt = 0; nt < 8; nt++) {
            int col = h * 64 + nt * 8 + 2 * qc;
            *(float2*)&Op[(b * TT + r0g) * CC + col] =
                make_float2(Of[nt][0], Of[nt][1]);
            *(float2*)&Op[(b * TT + r0g + 8) * CC + col] =
                make_float2(Of[nt][2], Of[nt][3]);
        }
        if (qc == 0) {
            int mlrow = (b * HH + h) * TT + r0g;
            g_m[part][mlrow] = m0;     g_l[part][mlrow] = l0;
            g_m[part][mlrow + 8] = m1; g_l[part][mlrow + 8] = l1;
        }
    }
}

// ---------------- kernel 2b: merge split-attention partials (t >= 1024) -----
__global__ void attn_merge_k() {
    int idx = blockIdx.x * 256 + threadIdx.x;
    const int total = BB * 1024 * CC;
    if (idx >= total) return;
    int b = idx / (1024 * CC);
    int rem = idx - b * 1024 * CC;
    int t = 1024 + rem / CC;
    int c = rem % CC;
    int h = c >> 6;
    int mlrow = (b * HH + h) * TT + t;
    float m1 = g_m[0][mlrow], m2 = g_m[1][mlrow];
    float l1 = g_l[0][mlrow], l2 = g_l[1][mlrow];
    float m = fmaxf(m1, m2);
    float a1 = __expf(m1 - m), a2 = __expf(m2 - m);
    float l = a1 * l1 + a2 * l2;
    int oidx = (b * TT + t) * CC + c;
    float o = (a1 * g_Op[0][oidx] + a2 * g_Op[1][oidx]) / l;
    g_Otf[oidx] = f2tf(o);
}

// ---------------- kernel 3: output projection (tf32 mma, cp.async) ----------
__global__ __launch_bounds__(256, 3) void out_proj_tc_k(
        const float* __restrict__ bo,
        float* __restrict__ out) {
    extern __shared__ unsigned smg[];
    unsigned* Xs = smg;
    unsigned* Ws = smg + 2 * 128 * XSTR;
    const int tid = threadIdx.x;
    const int w = tid >> 5, lane = tid & 31;
    const int qr = lane >> 2, qc = lane & 3;
    const int m0 = blockIdx.y * 128;
    const int nblk = blockIdx.x;
    const int n0 = nblk * 64;
    const int lrow = tid >> 1, lkb = (tid & 1) << 4;
    const int lkr = tid >> 4, lnb = (tid & 15) << 3;

    {
        unsigned* xd = &Xs[lrow * XSTR + lkb];
        const unsigned* xs = &g_Otf[(m0 + lrow) * CC + lkb];
#pragma unroll
        for (int q = 0; q < 4; q++) cp16(xd + q * 4, xs + q * 4);
        unsigned* wd = &Ws[lkr * PRSTR + lnb];
        const unsigned* ws = &g_Wo[(0 * 12 + nblk) * 16 * 128 + lkr * 128 + lnb];
#pragma unroll
        for (int q = 0; q < 2; q++) cp16(wd + q * 4, ws + q * 4);
        CP_COMMIT();
    }
    CP_WAIT0();
    __syncthreads();

    float Cf[8][4] = {};
    const int NCH = CC / 32;
    for (int c = 0; c < NCH; c++) {
        if (c + 1 < NCH) {
            int k0 = (c + 1) * 32;
            unsigned* Xn = Xs + ((c + 1) & 1) * 128 * XSTR;
            unsigned* Wn = Ws + ((c + 1) & 1) * 16 * PRSTR;
            unsigned* xd = &Xn[lrow * XSTR + lkb];
            const unsigned* xs = &g_Otf[(m0 + lrow) * CC + k0 + lkb];
#pragma unroll
            for (int q = 0; q < 4; q++) cp16(xd + q * 4, xs + q * 4);
            unsigned* wd = &Wn[lkr * PRSTR + lnb];
            const unsigned* ws =
                &g_Wo[((c + 1) * 12 + nblk) * 16 * 128 + lkr * 128 + lnb];
#pragma unroll
            for (int q = 0; q < 2; q++) cp16(wd + q * 4, ws + q * 4);
            CP_COMMIT();
        }
        const unsigned* Xb = Xs + (c & 1) * 128 * XSTR;
        const unsigned* Wb = Ws + (c & 1) * 16 * PRSTR;
        GEMM_CHUNK_MMAS(Xb, Wb)
        CP_WAIT0();
        __syncthreads();
    }

    const int r0 = m0 + w * 16 + qr;
#pragma unroll
    for (int nt = 0; nt < 8; nt++) {
        int n = n0 + nt * 8 + 2 * qc;
        float bv0 = bo[n], bv1 = bo[n + 1];
        *(float2*)&out[r0 * CC + n] =
            make_float2(Cf[nt][0] + bv0, Cf[nt][1] + bv1);
        *(float2*)&out[(r0 + 8) * CC + n] =
            make_float2(Cf[nt][2] + bv0, Cf[nt][3] + bv1);
    }
}

// ---------------- launcher ---------------------------------------------------
extern "C" void kernel_launch(void* const* d_in, const int* in_sizes, int n_in,
                              void* d_out, int out_size) {
    const float* x  = (const float*)d_in[0];
    const float* wq = (const float*)d_in[1];
    const float* bq = (const float*)d_in[2];
    const float* wk = (const float*)d_in[3];
    const float* bk = (const float*)d_in[4];
    const float* wv = (const float*)d_in[5];
    const float* bv = (const float*)d_in[6];
    const float* wo = (const float*)d_in[7];
    const float* bo = (const float*)d_in[8];
    float* out = (float*)d_out;

    cudaFuncSetAttribute(attn_k, cudaFuncAttributeMaxDynamicSharedMemorySize,
                         ATTN_SMEM_BYTES);
    cudaFuncSetAttribute(qkv_tc_k, cudaFuncAttributeMaxDynamicSharedMemorySize,
                         GEMM_SMEM_BYTES);
    cudaFuncSetAttribute(out_proj_tc_k,
                         cudaFuncAttributeMaxDynamicSharedMemorySize,
                         GEMM_SMEM_BYTES);

    pack_w_k<<<(CC * NQKV + 255) / 256, 256>>>(wq, wk, wv);
    pack_wo_k<<<(CC * CC + 255) / 256, 256>>>(wo);
    xconv_k<<<(BB * TT * CC + 255) / 256, 256>>>(x);
    rope_table_k<<<(TT * 32 + 255) / 256, 256>>>();
    qkv_tc_k<<<dim3(NQKV / 64, (BB * TT) / 128), 256, GEMM_SMEM_BYTES>>>(bq, bk, bv);
    attn_k<<<dim3(BB * HH, 24), 256, ATTN_SMEM_BYTES>>>();
    attn_merge_k<<<(BB * 1024 * CC + 255) / 256, 256>>>();
    out_proj_tc_k<<<dim3(CC / 64, (BB * TT) / 128), 256, GEMM_SMEM_BYTES>>>(bo, out);
}

// round 15
// speedup vs baseline: 1.1669x; 1.1669x over previous
#include <cuda_runtime.h>
#include <math.h>

#define BB 2
#define TT 2048
#define HH 12
#define DD 64
#define CC 768
#define NQKV 2304
#define NEG (-1e30f)

// ---------------- scratch (device globals; no allocations allowed) ----------
// W layouts: [kchunk][nblk][16 pair-rows][128 words]; pair-row = kt*4+qcK,
// word = nl*2 + lohi  (pair = k values kt*8+qcK and kt*8+qcK+4)
__device__ __align__(16) unsigned g_Wqkv[CC * NQKV];
__device__ __align__(16) unsigned g_Wo[CC * CC];
__device__ __align__(16) unsigned g_Xtf[BB * TT * CC];            // tf32 x
__device__ __align__(16) unsigned g_QKVt[3 * BB * HH * TT * DD];  // tf32 natural
__device__ __align__(16) unsigned g_Otf[BB * TT * CC];            // tf32 O
__device__ __align__(16) float    g_cos[TT * 32];
__device__ __align__(16) float    g_sin[TT * 32];
// split-attention partials (rows t>=1024 only are used)
__device__ __align__(16) float    g_Op[2][BB * TT * CC];
__device__ __align__(16) float    g_m[2][BB * HH * TT];
__device__ __align__(16) float    g_l[2][BB * HH * TT];

// ---------------- helpers ----------------------------------------------------
__device__ __forceinline__ unsigned f2tf(float f) {
    unsigned u;
    asm("cvt.rna.tf32.f32 %0, %1;" : "=r"(u) : "f"(f));
    return u;
}

__device__ __forceinline__ void mma_tf32(
        float& c0, float& c1, float& c2, float& c3,
        unsigned a0, unsigned a1, unsigned a2, unsigned a3,
        unsigned b0, unsigned b1) {
    asm("mma.sync.aligned.m16n8k8.row.col.f32.tf32.tf32.f32 "
        "{%0,%1,%2,%3}, {%4,%5,%6,%7}, {%8,%9}, {%0,%1,%2,%3};"
        : "+f"(c0), "+f"(c1), "+f"(c2), "+f"(c3)
        : "r"(a0), "r"(a1), "r"(a2), "r"(a3), "r"(b0), "r"(b1));
}

__device__ __forceinline__ void cp16(void* sdst, const void* gsrc) {
    unsigned s = (unsigned)__cvta_generic_to_shared(sdst);
    asm volatile("cp.async.cg.shared.global [%0], [%1], 16;" :: "r"(s), "l"(gsrc));
}
#define CP_COMMIT() asm volatile("cp.async.commit_group;")
#define CP_WAIT0()  asm volatile("cp.async.wait_group 0;")

// ---------------- kernel 0a: pack QKV weights (tf32, pair-interleaved) ------
__global__ void pack_w_k(const float* __restrict__ wq,
                         const float* __restrict__ wk,
                         const float* __restrict__ wv) {
    int idx = blockIdx.x * 256 + threadIdx.x;
    if (idx >= CC * NQKV) return;
    int k = idx / NQKV, n = idx - k * NQKV;
    int which = n / 768, hd = n - which * 768;
    int h = hd >> 6, d = hd & 63;
    const float* w = (which == 0) ? wq : (which == 1) ? wk : wv;
    int kc = k >> 5, kin = k & 31, kt = kin >> 3, kq = kin & 7;
    int qcK = kq & 3, lohi = kq >> 2;
    int nblk = n >> 6, nl = n & 63;
    int gidx = ((kc * 36 + nblk) * 16 + kt * 4 + qcK) * 128 + nl * 2 + lohi;
    g_Wqkv[gidx] = f2tf(w[(h * CC + k) * DD + d]);
}

// ---------------- kernel 0b: W_O pack (pair-interleaved) ---------------------
__global__ void pack_wo_k(const float* __restrict__ wo) {
    int idx = blockIdx.x * 256 + threadIdx.x;
    if (idx >= CC * CC) return;
    int k = idx / CC, n = idx - k * CC;
    int kc = k >> 5, kin = k & 31, kt = kin >> 3, kq = kin & 7;
    int qcK = kq & 3, lohi = kq >> 2;
    int nblk = n >> 6, nl = n & 63;
    int gidx = ((kc * 12 + nblk) * 16 + kt * 4 + qcK) * 128 + nl * 2 + lohi;
    g_Wo[gidx] = f2tf(wo[idx]);
}

// ---------------- kernel 0c: x -> tf32 ---------------------------------------
__global__ void xconv_k(const float* __restrict__ x) {
    int idx = blockIdx.x * 256 + threadIdx.x;
    if (idx >= BB * TT * CC) return;
    g_Xtf[idx] = f2tf(x[idx]);
}

// ---------------- kernel 0d: rope cos/sin table -----------------------------
__global__ void rope_table_k() {
    int idx = blockIdx.x * 256 + threadIdx.x;
    if (idx >= TT * 32) return;
    int t = idx >> 5, i = idx & 31;
    double e = (double)i * 0.41524101186092028;   // log2(10000)/32
    float inv = exp2f((float)(-e));
    float ang = (float)t * inv;
    float s, c;
    sincosf(ang, &s, &c);
    g_cos[idx] = c;
    g_sin[idx] = s;
}

// ---------------- tf32 GEMM: 128x128 tile, chunk 32, cp.async pipelined -----
#define XSTR 36
#define PRSTR 136
#define GEMM_SMEM_UINTS (2 * 128 * XSTR + 2 * 2 * 16 * PRSTR)
#define GEMM_SMEM_BYTES (GEMM_SMEM_UINTS * 4)

// mainloop chunk: scalar A frags, uint2 B pairs consumed immediately; 2 n-blks
#define GEMM_CHUNK_MMAS(Xb, Wb)                                              \
    _Pragma("unroll")                                                        \
    for (int kt = 0; kt < 4; kt++) {                                         \
        int abase = (w * 16 + qr) * XSTR + kt * 8 + qc;                      \
        unsigned fa0 = (Xb)[abase];                                          \
        unsigned fa1 = (Xb)[abase + 8 * XSTR];                               \
        unsigned fa2 = (Xb)[abase + 4];                                      \
        unsigned fa3 = (Xb)[abase + 8 * XSTR + 4];                           \
        const unsigned* wr0 = &(Wb)[(kt * 4 + qc) * PRSTR + qr * 2];         \
        const unsigned* wr1 = wr0 + 16 * PRSTR;                              \
        _Pragma("unroll")                                                    \
        for (int nt = 0; nt < 8; nt++) {                                     \
            uint2 bp = *(const uint2*)&wr0[nt * 16];                         \
            mma_tf32(Cf[nt][0], Cf[nt][1], Cf[nt][2], Cf[nt][3],             \
                     fa0, fa1, fa2, fa3, bp.x, bp.y);                        \
        }                                                                    \
        _Pragma("unroll")                                                    \
        for (int nt = 0; nt < 8; nt++) {                                     \
            uint2 bp = *(const uint2*)&wr1[nt * 16];                         \
            mma_tf32(Cf[8 + nt][0], Cf[8 + nt][1], Cf[8 + nt][2],            \
                     Cf[8 + nt][3], fa0, fa1, fa2, fa3, bp.x, bp.y);         \
        }                                                                    \
    }

// W tile async load: 2 nblks x 16 pair-rows x 128 words (4 cp16 per thread)
#define LOAD_W_TILE(Wdst, gW, chunk, nblk2, NBLKS)                           \
    _Pragma("unroll")                                                        \
    for (int p = 0; p < 4; p++) {                                            \
        int id = tid + 256 * p;                                              \
        int nb = id >> 9;                                                    \
        int rowid = (id >> 5) & 15;                                          \
        int word16 = (id & 31) << 2;                                         \
        cp16(&(Wdst)[nb * 16 * PRSTR + rowid * PRSTR + word16],              \
             &(gW)[(((chunk) * (NBLKS)) + ((nblk2) * 2 + nb)) * 2048 +       \
                   rowid * 128 + word16]);                                   \
    }

// ---------------- kernel 1: QKV GEMM + bias + RoPE (tf32 mma) ---------------
__global__ __launch_bounds__(256, 2) void qkv_tc_k(
        const float* __restrict__ bq,
        const float* __restrict__ bk,
        const float* __restrict__ bv) {
    extern __shared__ unsigned smg[];
    unsigned* Xs = smg;                        // 2 * 128*36
    unsigned* Ws = smg + 2 * 128 * XSTR;       // 2 * 2*16*136
    const int tid = threadIdx.x;
    const int w = tid >> 5, lane = tid & 31;
    const int qr = lane >> 2, qc = lane & 3;
    const int m0 = blockIdx.y * 128;
    const int nblk2 = blockIdx.x;
    const int n0 = nblk2 * 128;
    const int lrow = tid >> 1, lkb = (tid & 1) << 4;

    {
        unsigned* xd = &Xs[lrow * XSTR + lkb];
        const unsigned* xs = &g_Xtf[(m0 + lrow) * CC + lkb];
#pragma unroll
        for (int q = 0; q < 4; q++) cp16(xd + q * 4, xs + q * 4);
        LOAD_W_TILE(Ws, g_Wqkv, 0, nblk2, 36)
        CP_COMMIT();
    }
    CP_WAIT0();
    __syncthreads();

    float Cf[16][4] = {};
    const int NCH = CC / 32;   // 24
    for (int c = 0; c < NCH; c++) {
        if (c + 1 < NCH) {
            int k0 = (c + 1) * 32;
            unsigned* Xn = Xs + ((c + 1) & 1) * 128 * XSTR;
            unsigned* Wn = Ws + ((c + 1) & 1) * 2 * 16 * PRSTR;
            unsigned* xd = &Xn[lrow * XSTR + lkb];
            const unsigned* xs = &g_Xtf[(m0 + lrow) * CC + k0 + lkb];
#pragma unroll
            for (int q = 0; q < 4; q++) cp16(xd + q * 4, xs + q * 4);
            LOAD_W_TILE(Wn, g_Wqkv, c + 1, nblk2, 36)
            CP_COMMIT();
        }
        const unsigned* Xb = Xs + (c & 1) * 128 * XSTR;
        const unsigned* Wb = Ws + (c & 1) * 2 * 16 * PRSTR;
        GEMM_CHUNK_MMAS(Xb, Wb)
        CP_WAIT0();
        __syncthreads();
    }

    // epilogue: bias + rope (+0.125 for Q) -> tf32 scatter to g_QKVt (natural)
    const int which = n0 / 768;
    const int nbase = n0 % 768;
    const float* bias = (which == 0) ? bq : (which == 1) ? bk : bv;
    const float qscale = (which == 0) ? 0.125f : 1.0f;
    const int r0 = m0 + w * 16 + qr;
#pragma unroll
    for (int nt = 0; nt < 16; nt++) {
        int nl = nbase + nt * 8 + 2 * qc;
        int h = nl >> 6, d = nl & 63;
        float bv0 = bias[nl], bv1 = bias[nl + 1];
        int ii = d >> 1;
#pragma unroll
        for (int half = 0; half < 2; half++) {
            int r = r0 + half * 8;
            int bb = r >> 11, t = r & 2047;
            float v0 = Cf[nt][2 * half + 0] + bv0;
            float v1 = Cf[nt][2 * half + 1] + bv1;
            if (which < 2) {
                float cth = g_cos[t * 32 + ii];
                float sth = g_sin[t * 32 + ii];
                float nv0 = v0 * cth - v1 * sth;
                float nv1 = v0 * sth + v1 * cth;
                v0 = nv0 * qscale; v1 = nv1 * qscale;
            }
            *(uint2*)&g_QKVt[(((which * BB + bb) * HH + h) * TT + t) * DD + d] =
                make_uint2(f2tf(v0), f2tf(v1));
        }
    }
}

// ---------------- kernel 2: causal flash attention (tf32, split-K balanced) -
#define KSTR 68
#define VSTR 72
#define PSTR 68
#define ATTN_SMEM_UINTS (2 * 64 * KSTR + 2 * 64 * VSTR + 8 * 16 * PSTR)
#define ATTN_SMEM_BYTES (ATTN_SMEM_UINTS * 4)

__global__ __launch_bounds__(256) void attn_k() {
    extern __shared__ unsigned smu[];
    unsigned* Ks = smu;                          // 2 * 64*68
    unsigned* Vs = smu + 2 * 64 * KSTR;          // 2 * 64*72
    unsigned* Ps = Vs + 2 * 64 * VSTR;           // 8 * 16*68

    const int tid = threadIdx.x;
    const int w = tid >> 5, lane = tid & 31;
    const int qr = lane >> 2, qc = lane & 3;

    const int by = blockIdx.y;
    int qi, part, nparts;
    if (by < 16) { qi = 15 - (by >> 1); part = by & 1; nparts = 2; }
    else         { qi = 23 - by;        part = 0;      nparts = 1; }
    const int bh = blockIdx.x;
    const int b = bh / HH, h = bh % HH;
    const int q0 = qi * 128;
    const int njt = 2 * qi + 2;
    const int jn = (nparts == 2) ? (qi + 1) : njt;
    const int j0 = part * jn;

    const unsigned* Qg = g_QKVt + ((0 * BB + b) * HH + h) * TT * DD;
    const unsigned* Kg = g_QKVt + ((1 * BB + b) * HH + h) * TT * DD;
    const unsigned* Vg = g_QKVt + ((2 * BB + b) * HH + h) * TT * DD;

    // prologue: async-fill tile j0 into buffer (j0&1)
    {
        unsigned* K0 = Ks + (j0 & 1) * 64 * KSTR;
        unsigned* V0 = Vs + (j0 & 1) * 64 * VSTR;
        const unsigned* ksrc = &Kg[j0 * 64 * DD];
        const unsigned* vsrc = &Vg[j0 * 64 * DD];
#pragma unroll
        for (int i = 0; i < 4; i++) {
            int id = tid + 256 * i;
            int row = id >> 4, c16 = (id & 15) << 2;
            cp16(&K0[row * KSTR + c16], &ksrc[row * DD + c16]);
            cp16(&V0[row * VSTR + c16], &vsrc[row * DD + c16]);
        }
        CP_COMMIT();
    }

    // Q fragments (already tf32, pre-scaled)
    unsigned Qf[8][4];
    {
        const unsigned* qb = &Qg[(q0 + w * 16 + qr) * DD];
#pragma unroll
        for (int kt = 0; kt < 8; kt++) {
            Qf[kt][0] = qb[kt * 8 + qc];
            Qf[kt][1] = qb[8 * DD + kt * 8 + qc];
            Qf[kt][2] = qb[kt * 8 + qc + 4];
            Qf[kt][3] = qb[8 * DD + kt * 8 + qc + 4];
        }
    }

    float Of[8][4] = {};
    float m0 = NEG, m1 = NEG, l0 = 0.0f, l1 = 0.0f;
    unsigned* Pw = Ps + w * 16 * PSTR;

    CP_WAIT0();
    __syncthreads();

    const int jend = j0 + jn;
    for (int j = j0; j < jend; j++) {
        // prefetch next tile into the other buffer
        if (j + 1 < jend) {
            unsigned* Kn = Ks + ((j + 1) & 1) * 64 * KSTR;
            unsigned* Vn = Vs + ((j + 1) & 1) * 64 * VSTR;
            const unsigned* ksrc = &Kg[(j + 1) * 64 * DD];
            const unsigned* vsrc = &Vg[(j + 1) * 64 * DD];
#pragma unroll
            for (int i = 0; i < 4; i++) {
                int id = tid + 256 * i;
                int row = id >> 4, c16 = (id & 15) << 2;
                cp16(&Kn[row * KSTR + c16], &ksrc[row * DD + c16]);
                cp16(&Vn[row * VSTR + c16], &vsrc[row * DD + c16]);
            }
            CP_COMMIT();
        }
        const unsigned* Kb = Ks + (j & 1) * 64 * KSTR;
        const unsigned* Vb = Vs + (j & 1) * 64 * VSTR;

        // S = Q K^T
        float Sf[8][4] = {};
#pragma unroll
        for (int nt = 0; nt < 8; nt++) {
#pragma unroll
            for (int kt = 0; kt < 8; kt++) {
                unsigned b0 = Kb[(nt * 8 + qr) * KSTR + kt * 8 + qc];
                unsigned b1 = Kb[(nt * 8 + qr) * KSTR + kt * 8 + qc + 4];
                mma_tf32(Sf[nt][0], Sf[nt][1], Sf[nt][2], Sf[nt][3],
                         Qf[kt][0], Qf[kt][1], Qf[kt][2], Qf[kt][3], b0, b1);
            }
        }

        if (j >= njt - 2) {   // global diagonal tiles
            int r0g = q0 + w * 16 + qr, r1g = r0g + 8;
#pragma unroll
            for (int nt = 0; nt < 8; nt++) {
                int c0g = j * 64 + nt * 8 + 2 * qc;
                if (c0g > r0g)     Sf[nt][0] = NEG;
                if (c0g + 1 > r0g) Sf[nt][1] = NEG;
                if (c0g > r1g)     Sf[nt][2] = NEG;
                if (c0g + 1 > r1g) Sf[nt][3] = NEG;
            }
        }

        // online softmax (quad of 4 lanes owns a row)
        float mx0 = NEG, mx1 = NEG;
#pragma unroll
        for (int nt = 0; nt < 8; nt++) {
            mx0 = fmaxf(mx0, fmaxf(Sf[nt][0], Sf[nt][1]));
            mx1 = fmaxf(mx1, fmaxf(Sf[nt][2], Sf[nt][3]));
        }
        mx0 = fmaxf(mx0, __shfl_xor_sync(0xffffffffu, mx0, 1));
        mx0 = fmaxf(mx0, __shfl_xor_sync(0xffffffffu, mx0, 2));
        mx1 = fmaxf(mx1, __shfl_xor_sync(0xffffffffu, mx1, 1));
        mx1 = fmaxf(mx1, __shfl_xor_sync(0xffffffffu, mx1, 2));
        float mn0 = fmaxf(m0, mx0), mn1 = fmaxf(m1, mx1);
        float al0 = __expf(m0 - mn0), al1 = __expf(m1 - mn1);
        m0 = mn0; m1 = mn1;
        float s0 = 0.0f, s1 = 0.0f;
#pragma unroll
        for (int nt = 0; nt < 8; nt++) {
            Sf[nt][0] = __expf(Sf[nt][0] - mn0); s0 += Sf[nt][0];
            Sf[nt][1] = __expf(Sf[nt][1] - mn0); s0 += Sf[nt][1];
            Sf[nt][2] = __expf(Sf[nt][2] - mn1); s1 += Sf[nt][2];
            Sf[nt][3] = __expf(Sf[nt][3] - mn1); s1 += Sf[nt][3];
        }
        s0 += __shfl_xor_sync(0xffffffffu, s0, 1);
        s0 += __shfl_xor_sync(0xffffffffu, s0, 2);
        s1 += __shfl_xor_sync(0xffffffffu, s1, 1);
        s1 += __shfl_xor_sync(0xffffffffu, s1, 2);
        l0 = l0 * al0 + s0;
        l1 = l1 * al1 + s1;
#pragma unroll
        for (int nt = 0; nt < 8; nt++) {
            Of[nt][0] *= al0; Of[nt][1] *= al0;
            Of[nt][2] *= al1; Of[nt][3] *= al1;
        }

        // P (tf32) to per-warp smem
#pragma unroll
        for (int nt = 0; nt < 8; nt++) {
            unsigned* p0 = &Pw[qr * PSTR + nt * 8 + 2 * qc];
            p0[0] = f2tf(Sf[nt][0]); p0[1] = f2tf(Sf[nt][1]);
            unsigned* p1 = &Pw[(qr + 8) * PSTR + nt * 8 + 2 * qc];
            p1[0] = f2tf(Sf[nt][2]); p1[1] = f2tf(Sf[nt][3]);
        }
        __syncwarp();

        // O += P V
#pragma unroll
        for (int kt = 0; kt < 8; kt++) {
            unsigned a0 = Pw[qr * PSTR + kt * 8 + qc];
            unsigned a1 = Pw[(qr + 8) * PSTR + kt * 8 + qc];
            unsigned a2 = Pw[qr * PSTR + kt * 8 + qc + 4];
            unsigned a3 = Pw[(qr + 8) * PSTR + kt * 8 + qc + 4];
#pragma unroll
            for (int nt = 0; nt < 8; nt++) {
                unsigned b0 = Vb[(kt * 8 + qc) * VSTR + nt * 8 + qr];
                unsigned b1 = Vb[(kt * 8 + qc + 4) * VSTR + nt * 8 + qr];
                mma_tf32(Of[nt][0], Of[nt][1], Of[nt][2], Of[nt][3],
                         a0, a1, a2, a3, b0, b1);
            }
        }

        CP_WAIT0();
        __syncthreads();
    }

    int r0g = q0 + w * 16 + qr;
    if (nparts == 1) {
        float il0 = 1.0f / l0, il1 = 1.0f / l1;
#pragma unroll
        for (int nt = 0; nt < 8; nt++) {
            int col = h * 64 + nt * 8 + 2 * qc;
            *(uint2*)&g_Otf[(b * TT + r0g) * CC + col] =
                make_uint2(f2tf(Of[nt][0] * il0), f2tf(Of[nt][1] * il0));
            *(uint2*)&g_Otf[(b * TT + r0g + 8) * CC + col] =
                make_uint2(f2tf(Of[nt][2] * il1), f2tf(Of[nt][3] * il1));
        }
    } else {
        float* Op = g_Op[part];
#pragma unroll
        for (int nt = 0; nt < 8; nt++) {
            int col = h * 64 + nt * 8 + 2 * qc;
            *(float2*)&Op[(b * TT + r0g) * CC + col] =
                make_float2(Of[nt][0], Of[nt][1]);
            *(float2*)&Op[(b * TT + r0g + 8) * CC + col] =
                make_float2(Of[nt][2], Of[nt][3]);
        }
        if (qc == 0) {
            int mlrow = (b * HH + h) * TT + r0g;
            g_m[part][mlrow] = m0;     g_l[part][mlrow] = l0;
            g_m[part][mlrow + 8] = m1; g_l[part][mlrow + 8] = l1;
        }
    }
}

// ---------------- kernel 2b: merge split-attention partials (t >= 1024) -----
__global__ void attn_merge_k() {
    int idx = blockIdx.x * 256 + threadIdx.x;
    const int total = BB * 1024 * CC;
    if (idx >= total) return;
    int b = idx / (1024 * CC);
    int rem = idx - b * 1024 * CC;
    int t = 1024 + rem / CC;
    int c = rem % CC;
    int h = c >> 6;
    int mlrow = (b * HH + h) * TT + t;
    float m1 = g_m[0][mlrow], m2 = g_m[1][mlrow];
    float l1 = g_l[0][mlrow], l2 = g_l[1][mlrow];
    float m = fmaxf(m1, m2);
    float a1 = __expf(m1 - m), a2 = __expf(m2 - m);
    float l = a1 * l1 + a2 * l2;
    int oidx = (b * TT + t) * CC + c;
    float o = (a1 * g_Op[0][oidx] + a2 * g_Op[1][oidx]) / l;
    g_Otf[oidx] = f2tf(o);
}

// ---------------- kernel 3: output projection (tf32 mma, cp.async) ----------
__global__ __launch_bounds__(256, 2) void out_proj_tc_k(
        const float* __restrict__ bo,
        float* __restrict__ out) {
    extern __shared__ unsigned smg[];
    unsigned* Xs = smg;
    unsigned* Ws = smg + 2 * 128 * XSTR;
    const int tid = threadIdx.x;
    const int w = tid >> 5, lane = tid & 31;
    const int qr = lane >> 2, qc = lane & 3;
    const int m0 = blockIdx.y * 128;
    const int nblk2 = blockIdx.x;
    const int n0 = nblk2 * 128;
    const int lrow = tid >> 1, lkb = (tid & 1) << 4;

    {
        unsigned* xd = &Xs[lrow * XSTR + lkb];
        const unsigned* xs = &g_Otf[(m0 + lrow) * CC + lkb];
#pragma unroll
        for (int q = 0; q < 4; q++) cp16(xd + q * 4, xs + q * 4);
        LOAD_W_TILE(Ws, g_Wo, 0, nblk2, 12)
        CP_COMMIT();
    }
    CP_WAIT0();
    __syncthreads();

    float Cf[16][4] = {};
    const int NCH = CC / 32;
    for (int c = 0; c < NCH; c++) {
        if (c + 1 < NCH) {
            int k0 = (c + 1) * 32;
            unsigned* Xn = Xs + ((c + 1) & 1) * 128 * XSTR;
            unsigned* Wn = Ws + ((c + 1) & 1) * 2 * 16 * PRSTR;
            unsigned* xd = &Xn[lrow * XSTR + lkb];
            const unsigned* xs = &g_Otf[(m0 + lrow) * CC + k0 + lkb];
#pragma unroll
            for (int q = 0; q < 4; q++) cp16(xd + q * 4, xs + q * 4);
            LOAD_W_TILE(Wn, g_Wo, c + 1, nblk2, 12)
            CP_COMMIT();
        }
        const unsigned* Xb = Xs + (c & 1) * 128 * XSTR;
        const unsigned* Wb = Ws + (c & 1) * 2 * 16 * PRSTR;
        GEMM_CHUNK_MMAS(Xb, Wb)
        CP_WAIT0();
        __syncthreads();
    }

    const int r0 = m0 + w * 16 + qr;
#pragma unroll
    for (int nt = 0; nt < 16; nt++) {
        int n = n0 + nt * 8 + 2 * qc;
        float bv0 = bo[n], bv1 = bo[n + 1];
        *(float2*)&out[r0 * CC + n] =
            make_float2(Cf[nt][0] + bv0, Cf[nt][1] + bv1);
        *(float2*)&out[(r0 + 8) * CC + n] =
            make_float2(Cf[nt][2] + bv0, Cf[nt][3] + bv1);
    }
}

// ---------------- launcher ---------------------------------------------------
extern "C" void kernel_launch(void* const* d_in, const int* in_sizes, int n_in,
                              void* d_out, int out_size) {
    const float* x  = (const float*)d_in[0];
    const float* wq = (const float*)d_in[1];
    const float* bq = (const float*)d_in[2];
    const float* wk = (const float*)d_in[3];
    const float* bk = (const float*)d_in[4];
    const float* wv = (const float*)d_in[5];
    const float* bv = (const float*)d_in[6];
    const float* wo = (const float*)d_in[7];
    const float* bo = (const float*)d_in[8];
    float* out = (float*)d_out;

    cudaFuncSetAttribute(attn_k, cudaFuncAttributeMaxDynamicSharedMemorySize,
                         ATTN_SMEM_BYTES);
    cudaFuncSetAttribute(qkv_tc_k, cudaFuncAttributeMaxDynamicSharedMemorySize,
                         GEMM_SMEM_BYTES);
    cudaFuncSetAttribute(out_proj_tc_k,
                         cudaFuncAttributeMaxDynamicSharedMemorySize,
                         GEMM_SMEM_BYTES);

    pack_w_k<<<(CC * NQKV + 255) / 256, 256>>>(wq, wk, wv);
    pack_wo_k<<<(CC * CC + 255) / 256, 256>>>(wo);
    xconv_k<<<(BB * TT * CC + 255) / 256, 256>>>(x);
    rope_table_k<<<(TT * 32 + 255) / 256, 256>>>();
    qkv_tc_k<<<dim3(NQKV / 128, (BB * TT) / 128), 256, GEMM_SMEM_BYTES>>>(bq, bk, bv);
    attn_k<<<dim3(BB * HH, 24), 256, ATTN_SMEM_BYTES>>>();
    attn_merge_k<<<(BB * 1024 * CC + 255) / 256, 256>>>();
    out_proj_tc_k<<<dim3(CC / 128, (BB * TT) / 128), 256, GEMM_SMEM_BYTES>>>(bo, out);
}